// round 1
// baseline (speedup 1.0000x reference)
#include <cuda_runtime.h>
#include <math.h>

#define Bq 4
#define Nq 2048
#define Kq 48
#define EC 128

// Scratch: gathered/masked token center coords, [B*N] as float4
__device__ float4 g_X[Bq * Nq];

// ---------------------------------------------------------------------------
// Kernel 1: gather center-atom coords, apply token mask
// ---------------------------------------------------------------------------
__global__ void gather_x_kernel(const float* __restrict__ coords,
                                const float* __restrict__ mask,
                                const int* __restrict__ center) {
    int t = blockIdx.x * blockDim.x + threadIdx.x;
    if (t >= Bq * Nq) return;
    int b = t / Nq;
    int c = center[t];
    float m = mask[t];
    const float* p = coords + ((size_t)b * Nq + c) * 3;
    g_X[t] = make_float4(p[0] * m, p[1] * m, p[2] * m, 0.f);
}

// ---------------------------------------------------------------------------
// Kernel 2: masked pairwise distances + exact top-K (smallest, jax tie order)
// via radix-select over u64 keys (float_bits(D_adjust)<<32 | j).
// One block per (b,i) row. 256 threads, 8 keys each (in registers).
// ---------------------------------------------------------------------------
__global__ __launch_bounds__(256) void knn_kernel(const float* __restrict__ mask,
                                                  float* __restrict__ outIdx,
                                                  float* __restrict__ outD) {
    __shared__ float Dsm[Nq];
    __shared__ unsigned int hist[256];
    __shared__ float warpred[8];
    __shared__ float s_Dmax;
    __shared__ int s_digit;
    __shared__ int s_rank;
    __shared__ unsigned long long cand[Kq];
    __shared__ int s_cnt;

    int row = blockIdx.x;
    int b = row / Nq;
    int tid = threadIdx.x;
    int lane = tid & 31, warp = tid >> 5;

    float4 xi = g_X[row];
    float mi = mask[row];
    const float* mrow = mask + b * Nq;

    // Pass 1: distances + row max
    float lmax = 0.f;
#pragma unroll
    for (int q = 0; q < Nq / 256; q++) {
        int j = tid + q * 256;
        float4 xj = g_X[b * Nq + j];
        float dx = xi.x - xj.x, dy = xi.y - xj.y, dz = xi.z - xj.z;
        float d = mi * mrow[j] * sqrtf(dx * dx + dy * dy + dz * dz + 1e-6f);
        Dsm[j] = d;
        lmax = fmaxf(lmax, d);
    }
    for (int o = 16; o; o >>= 1) lmax = fmaxf(lmax, __shfl_xor_sync(~0u, lmax, o));
    if (lane == 0) warpred[warp] = lmax;
    __syncthreads();
    if (tid == 0) {
        float m = warpred[0];
#pragma unroll
        for (int w = 1; w < 8; w++) m = fmaxf(m, warpred[w]);
        s_Dmax = m;
        s_rank = Kq;
        s_cnt = 0;
    }
    __syncthreads();
    float Dmax = s_Dmax;

    // Pass 2: build u64 keys in registers (D_adjust bits << 32 | index)
    unsigned long long kreg[Nq / 256];
#pragma unroll
    for (int q = 0; q < Nq / 256; q++) {
        int j = tid + q * 256;
        float m2 = mi * mrow[j];
        float adj = Dsm[j] + (1.f - m2) * Dmax;
        kreg[q] = ((unsigned long long)__float_as_uint(adj) << 32) | (unsigned)j;
    }

    // Radix select: find the Kq-th smallest key exactly.
    // Digits: bits [63:56],[55:48],[47:40],[39:32],[15:8],[7:0]
    // (bits 31:16 are zero for all keys since j < 2048).
    unsigned long long prefix = 0, pmask = 0;
    const int shifts[6] = {56, 48, 40, 32, 8, 0};
#pragma unroll 1
    for (int r = 0; r < 6; r++) {
        int sh = shifts[r];
        hist[tid] = 0;
        __syncthreads();
#pragma unroll
        for (int q = 0; q < Nq / 256; q++)
            if ((kreg[q] & pmask) == prefix)
                atomicAdd(&hist[(unsigned)(kreg[q] >> sh) & 255u], 1u);
        __syncthreads();
        if (tid < 32) {
            int base = tid * 8;
            unsigned cnts[8];
            unsigned p = 0;
#pragma unroll
            for (int q2 = 0; q2 < 8; q2++) { cnts[q2] = hist[base + q2]; p += cnts[q2]; }
            unsigned incl = p;
            for (int o = 1; o < 32; o <<= 1) {
                unsigned v = __shfl_up_sync(~0u, incl, o);
                if (tid >= o) incl += v;
            }
            unsigned excl = incl - p;
            int rk = s_rank;
            __syncwarp();
            if ((int)excl < rk && rk <= (int)incl) {
                int rr = rk - (int)excl;
#pragma unroll
                for (int q2 = 0; q2 < 8; q2++) {
                    if (rr <= (int)cnts[q2]) { s_digit = base + q2; s_rank = rr; break; }
                    rr -= (int)cnts[q2];
                }
            }
        }
        __syncthreads();
        prefix |= ((unsigned long long)s_digit) << sh;
        pmask |= 0xFFull << sh;
    }
    // prefix == exact Kq-th smallest key. Gather all keys <= prefix (exactly Kq,
    // keys are distinct since the index is embedded).
#pragma unroll
    for (int q = 0; q < Nq / 256; q++)
        if (kreg[q] <= prefix) {
            int pos = atomicAdd(&s_cnt, 1);
            if (pos < Kq) cand[pos] = kreg[q];
        }
    __syncthreads();
    if (tid < Kq) {
        unsigned long long k = cand[tid];
        int rk = 0;
#pragma unroll
        for (int s = 0; s < Kq; s++) rk += (cand[s] < k);
        int j = (int)(unsigned)(k & 0xFFFFFFFFull);
        outIdx[(size_t)row * Kq + rk] = (float)j;
        outD[(size_t)row * Kq + rk] = __uint_as_float((unsigned)(k >> 32));
    }
}

// ---------------------------------------------------------------------------
// Kernel 3: edge features [48 x 33] -> GEMM with edge_w [33 x 128] -> LayerNorm
// One 128-thread block per (b,i). Thread = output channel; W column in regs.
// ---------------------------------------------------------------------------
__global__ __launch_bounds__(128) void edge_kernel(
    const float* __restrict__ eidx, const float* __restrict__ dnb,
    const int* __restrict__ resi, const int* __restrict__ lig,
    const float* __restrict__ bonds,
    const float* __restrict__ pe_w, const float* __restrict__ pe_b,
    const float* __restrict__ edge_w,
    const float* __restrict__ ln_g, const float* __restrict__ ln_b,
    float* __restrict__ outE) {
    __shared__ __align__(16) float f[Kq][36];
    __shared__ float red[16][4][2];
    __shared__ float stats[16][2];

    int c = threadIdx.x;
    int lane = c & 31, warp = c >> 5;
    int row = blockIdx.x;
    int b = row / Nq, i = row % Nq;

    float w[36];
#pragma unroll
    for (int t = 0; t < 33; t++) w[t] = edge_w[t * EC + c];
    w[33] = w[34] = w[35] = 0.f;
    float gg = ln_g[c], bb = ln_b[c];

    int ri = resi[row];
    int li = lig[row];
    const float* brow = bonds + ((size_t)b * Nq + i) * Nq;

    // Build feature rows (threads 0..47, one edge each)
    if (c < Kq) {
        int k = c;
        float fv = eidx[(size_t)row * Kq + k];
        int j = (int)fv;
        float dk = dnb[(size_t)row * Kq + k];
        // chain_labels are all-zero in the reference => E_chains == 1 always
        int d = ri - resi[b * Nq + j] + 32;
        d = max(0, min(64, d));
#pragma unroll
        for (int t = 0; t < 16; t++) f[k][t] = pe_w[d * 16 + t] + pe_b[t];
#pragma unroll
        for (int m = 0; m < 16; m++) {
            float mu = 2.f + (20.f / 15.f) * (float)m;
            float x = (dk - mu) * 0.8f;  // 1/1.25
            f[k][16 + m] = __expf(-x * x);
        }
        float tb = brow[j];
        f[k][32] = (li | lig[b * Nq + j]) ? tb : 0.f;
        f[k][33] = f[k][34] = f[k][35] = 0.f;
    }
    __syncthreads();

    for (int k0 = 0; k0 < Kq; k0 += 16) {
        float e[16];
#pragma unroll
        for (int kk = 0; kk < 16; kk++) {
            const float4* fp = (const float4*)f[k0 + kk];
            float acc = 0.f;
#pragma unroll
            for (int q = 0; q < 9; q++) {
                float4 v = fp[q];
                acc += v.x * w[4 * q] + v.y * w[4 * q + 1] + v.z * w[4 * q + 2] +
                       v.w * w[4 * q + 3];
            }
            e[kk] = acc;
        }
        // LN reductions: warp partials -> smem -> finalize
#pragma unroll
        for (int kk = 0; kk < 16; kk++) {
            float s = e[kk], s2 = e[kk] * e[kk];
            for (int o = 16; o; o >>= 1) {
                s += __shfl_xor_sync(~0u, s, o);
                s2 += __shfl_xor_sync(~0u, s2, o);
            }
            if (lane == 0) { red[kk][warp][0] = s; red[kk][warp][1] = s2; }
        }
        __syncthreads();
        if (c < 16) {
            float s = red[c][0][0] + red[c][1][0] + red[c][2][0] + red[c][3][0];
            float s2 = red[c][0][1] + red[c][1][1] + red[c][2][1] + red[c][3][1];
            float mean = s * (1.f / EC);
            float var = s2 * (1.f / EC) - mean * mean;
            stats[c][0] = mean;
            stats[c][1] = rsqrtf(var + 1e-5f);
        }
        __syncthreads();
        size_t baseo = ((size_t)row * Kq + k0) * EC + c;
#pragma unroll
        for (int kk = 0; kk < 16; kk++) {
            float mean = stats[kk][0], rstd = stats[kk][1];
            outE[baseo + (size_t)kk * EC] = (e[kk] - mean) * rstd * gg + bb;
        }
        __syncthreads();
    }
}

// ---------------------------------------------------------------------------
extern "C" void kernel_launch(void* const* d_in, const int* in_sizes, int n_in,
                              void* d_out, int out_size) {
    const float* coords = (const float*)d_in[0];
    const float* mask   = (const float*)d_in[1];
    const float* bonds  = (const float*)d_in[2];
    const float* pe_w   = (const float*)d_in[3];
    const float* pe_b   = (const float*)d_in[4];
    const float* edge_w = (const float*)d_in[5];
    const float* ln_g   = (const float*)d_in[6];
    const float* ln_b   = (const float*)d_in[7];
    const int* center   = (const int*)d_in[8];
    const int* resi     = (const int*)d_in[9];
    // d_in[10] = asym_id (unused: chain encoding disabled in reference)
    const int* lig      = (const int*)d_in[11];

    float* outE = (float*)d_out;
    size_t nE = (size_t)Bq * Nq * Kq * EC;        // 50,331,648
    float* outIdx = outE + nE;                    // E_idx as float
    float* outD = outIdx + (size_t)Bq * Nq * Kq;  // D_neighbors

    gather_x_kernel<<<(Bq * Nq + 255) / 256, 256>>>(coords, mask, center);
    knn_kernel<<<Bq * Nq, 256>>>(mask, outIdx, outD);
    edge_kernel<<<Bq * Nq, 128>>>(outIdx, outD, resi, lig, bonds, pe_w, pe_b,
                                  edge_w, ln_g, ln_b, outE);
}